// round 1
// baseline (speedup 1.0000x reference)
#include <cuda_runtime.h>

#define THREADS 512
#define RPB     8          // batch rows per CTA
#define NCTA    128        // 1024 / 8
#define HID     128
#define GATES   512        // 4*HID
#define KS      96         // k-rows of Wh held in smem
#define KR      32         // k-rows of Wh held in registers (KS+KR=128)
#define SEQ     1024
#define BATCH   1024

// smem (floats): W_s[KS][512] | hbuf[128][8] | g_s[8][512] | wd_s[128] | xbuf[8]
#define SMEM_FLOATS (KS*GATES + HID*RPB + RPB*GATES + HID + RPB)

typedef unsigned long long u64;

__device__ __forceinline__ u64 pack2(float lo, float hi) {
    u64 r;
    asm("mov.b64 %0, {%1, %2};" : "=l"(r) : "f"(lo), "f"(hi));
    return r;
}
__device__ __forceinline__ void unpack2(u64 v, float& lo, float& hi) {
    asm("mov.b64 {%0, %1}, %2;" : "=f"(lo), "=f"(hi) : "l"(v));
}
// d = a*b + d, two packed fp32 lanes (Blackwell native 2xFP32 path)
__device__ __forceinline__ void fma2(u64& d, u64 a, u64 b) {
    asm("fma.rn.f32x2 %0, %1, %2, %0;" : "+l"(d) : "l"(a), "l"(b));
}

__device__ __forceinline__ float fast_sigmoid(float x) {
    x = fminf(fmaxf(x, -30.f), 30.f);
    float e = __expf(-x);                 // ex2-based, ~1e-7 rel err
    return __fdividef(1.f, 1.f + e);      // rcp-based
}
__device__ __forceinline__ float fast_tanh(float x) {
    x = fminf(fmaxf(x, -15.f), 15.f);     // tanh(15) == 1.0f in fp32
    float e = __expf(2.f * x);
    return __fdividef(e - 1.f, e + 1.f);
}

__global__ void __launch_bounds__(THREADS, 1)
lstm_fused_kernel(const float* __restrict__ x,  const float* __restrict__ Wi,
                  const float* __restrict__ Wh, const float* __restrict__ b,
                  const float* __restrict__ Wd, const float* __restrict__ bd,
                  float* __restrict__ out)
{
    extern __shared__ float sm[];
    float* W_s  = sm;                       // [KS][GATES]
    float* hbuf = W_s  + KS * GATES;        // [HID][RPB], 16B-aligned
    float* g_s  = hbuf + HID * RPB;         // [RPB][GATES]
    float* wd_s = g_s  + RPB * GATES;       // [HID]
    float* xbuf = wd_s + HID;               // [RPB]

    const int t  = threadIdx.x;
    const int j  = t;                       // gate column owned by this thread
    const int r0 = blockIdx.x * RPB;        // first global batch row

    // ---- load Wh: 96 rows into smem (coalesced), 32 rows into registers ----
    for (int k = 0; k < KS; k++)
        W_s[k * GATES + t] = Wh[k * GATES + t];

    float wreg[KR];
#pragma unroll
    for (int kk = 0; kk < KR; kk++)
        wreg[kk] = Wh[(KS + kk) * GATES + j];

    const float wi = Wi[j];
    const float bj = b[j];

    for (int idx = t; idx < HID * RPB; idx += THREADS) hbuf[idx] = 0.f;
    if (t < HID) wd_s[t] = Wd[t];

    // ---- persistent cell state (update role): items (up_r, up_hi), (up_r+4, up_hi)
    float c_a = 0.f, c_b = 0.f;
    const int up_r  = t >> 7;               // 0..3
    const int up_hi = t & 127;

    const bool is_g_gate = (j >= 2 * HID) && (j < 3 * HID);  // warp-uniform

    // x prefetch (one step ahead, LDG latency hidden across the step body)
    float xnext = 0.f;
    if (t < RPB) xnext = x[(r0 + t) * SEQ + 0];

    const ulonglong2* hb = reinterpret_cast<const ulonglong2*>(hbuf);

    for (int s = 0; s < SEQ; s++) {
        if (t < RPB) {
            xbuf[t] = xnext;
            if (s + 1 < SEQ) xnext = x[(r0 + t) * SEQ + s + 1];
        }
        __syncthreads();   // hbuf(prev update) + xbuf ready; g_s consumers done

        // ---- gates[j][r] = x[r]*Wi[j] + b[j] + sum_k h[r][k]*Wh[k][j] ----
        u64 acc01 = pack2(fmaf(xbuf[0], wi, bj), fmaf(xbuf[1], wi, bj));
        u64 acc23 = pack2(fmaf(xbuf[2], wi, bj), fmaf(xbuf[3], wi, bj));
        u64 acc45 = pack2(fmaf(xbuf[4], wi, bj), fmaf(xbuf[5], wi, bj));
        u64 acc67 = pack2(fmaf(xbuf[6], wi, bj), fmaf(xbuf[7], wi, bj));

#pragma unroll 16
        for (int k = 0; k < KS; k++) {
            float w = W_s[k * GATES + j];
            u64  w2 = pack2(w, w);
            ulonglong2 hA = hb[2 * k];       // h[r0..r3] broadcast LDS.128
            ulonglong2 hB = hb[2 * k + 1];   // h[r4..r7]
            fma2(acc01, w2, hA.x);
            fma2(acc23, w2, hA.y);
            fma2(acc45, w2, hB.x);
            fma2(acc67, w2, hB.y);
        }
#pragma unroll
        for (int kk = 0; kk < KR; kk++) {
            u64  w2 = pack2(wreg[kk], wreg[kk]);
            ulonglong2 hA = hb[2 * (KS + kk)];
            ulonglong2 hB = hb[2 * (KS + kk) + 1];
            fma2(acc01, w2, hA.x);
            fma2(acc23, w2, hA.y);
            fma2(acc45, w2, hB.x);
            fma2(acc67, w2, hB.y);
        }

        // ---- activations (warp-uniform gate type), store to g_s[r][col] ----
        float gv[RPB];
        unpack2(acc01, gv[0], gv[1]);
        unpack2(acc23, gv[2], gv[3]);
        unpack2(acc45, gv[4], gv[5]);
        unpack2(acc67, gv[6], gv[7]);
        if (is_g_gate) {
#pragma unroll
            for (int r = 0; r < RPB; r++) gv[r] = fast_tanh(gv[r]);
        } else {
#pragma unroll
            for (int r = 0; r < RPB; r++) gv[r] = fast_sigmoid(gv[r]);
        }
#pragma unroll
        for (int r = 0; r < RPB; r++) g_s[r * GATES + j] = gv[r];

        __syncthreads();   // gates visible to update role

        // ---- cell/hidden update: c = f*c + i*g ; h = o*tanh(c) ----
        {
            const float* gr = g_s + up_r * GATES;
            float iv = gr[up_hi];
            float fv = gr[HID + up_hi];
            float gg = gr[2 * HID + up_hi];
            float ov = gr[3 * HID + up_hi];
            c_a = fv * c_a + iv * gg;
            hbuf[up_hi * RPB + up_r] = ov * fast_tanh(c_a);

            const float* gr2 = g_s + (up_r + 4) * GATES;
            float iv2 = gr2[up_hi];
            float fv2 = gr2[HID + up_hi];
            float gg2 = gr2[2 * HID + up_hi];
            float ov2 = gr2[3 * HID + up_hi];
            c_b = fv2 * c_b + iv2 * gg2;
            hbuf[up_hi * RPB + (up_r + 4)] = ov2 * fast_tanh(c_b);
        }
        // next iteration's __syncthreads() orders hbuf writes before reads
    }
    __syncthreads();

    // ---- output: out[r] = sum_k h[r][k] * Wd[k] + bd ----
    if (t < 256) {
        int rr = t >> 5, lane = t & 31;
        float sum = 0.f;
#pragma unroll
        for (int q = 0; q < 4; q++)
            sum += hbuf[(lane + 32 * q) * RPB + rr] * wd_s[lane + 32 * q];
#pragma unroll
        for (int off = 16; off; off >>= 1)
            sum += __shfl_down_sync(0xffffffffu, sum, off);
        if (lane == 0) out[r0 + rr] = sum + bd[0];
    }
}

extern "C" void kernel_launch(void* const* d_in, const int* in_sizes, int n_in,
                              void* d_out, int out_size)
{
    (void)in_sizes; (void)n_in; (void)out_size;
    const float* x  = (const float*)d_in[0];
    const float* Wi = (const float*)d_in[1];
    const float* Wh = (const float*)d_in[2];
    const float* b  = (const float*)d_in[3];
    const float* Wd = (const float*)d_in[4];
    const float* bd = (const float*)d_in[5];
    float* out = (float*)d_out;

    size_t smem = SMEM_FLOATS * sizeof(float);  // 217,632 B < 227 KB limit
    cudaFuncSetAttribute(lstm_fused_kernel,
                         cudaFuncAttributeMaxDynamicSharedMemorySize, (int)smem);
    lstm_fused_kernel<<<NCTA, THREADS, smem>>>(x, Wi, Wh, b, Wd, bd, out);
}

// round 3
// speedup vs baseline: 2.1470x; 2.1470x over previous
#include <cuda_runtime.h>
#include <cuda_fp16.h>
#include <cuda_fp8.h>

#define THREADS 512
#define RPB     8
#define NCTA    128
#define SEQ     1024
#define GATES   512
#define HID     128

// ---- smem byte offsets ----
#define AH_OFF    0         // A_hi fp16 fragments: 256 frags * 512B = 131072
#define ALO_OFF   131072    // A_lo e4m3 fragments: 128 frags * 512B = 65536
#define BH_OFF    196608    // B_hi fp16 frags: 8 * 256B
#define BL_OFF    198656    // B_lo fp16 frags: 8 * 256B
#define B8_OFF    200704    // B   e4m3 frags: 4 * 256B
#define GS_OFF    201728    // activated gates [8 cols][512 rows] f32 = 16384
#define XBUF_OFF  218112    // x double buffer 2*8 f32
#define RED_OFF   218176    // output reduction 128*8 f32
#define SMEM_TOTAL 222272

#define SCALE_LO     4096.0f
#define INV_SCALE_LO 0.000244140625f

typedef unsigned int u32;

// ---------------- mma wrappers (family-safe: sm_80 / sm_89) ----------------
static __device__ __forceinline__ void mma_f16(float* d, const uint4& a, const uint2& b) {
    asm volatile("mma.sync.aligned.m16n8k16.row.col.f32.f16.f16.f32 "
        "{%0,%1,%2,%3}, {%4,%5,%6,%7}, {%8,%9}, {%0,%1,%2,%3};"
        : "+f"(d[0]), "+f"(d[1]), "+f"(d[2]), "+f"(d[3])
        : "r"(a.x), "r"(a.y), "r"(a.z), "r"(a.w), "r"(b.x), "r"(b.y));
}
static __device__ __forceinline__ void mma_e4m3(float* d, const uint4& a, const uint2& b) {
    asm volatile("mma.sync.aligned.m16n8k32.row.col.f32.e4m3.e4m3.f32 "
        "{%0,%1,%2,%3}, {%4,%5,%6,%7}, {%8,%9}, {%0,%1,%2,%3};"
        : "+f"(d[0]), "+f"(d[1]), "+f"(d[2]), "+f"(d[3])
        : "r"(a.x), "r"(a.y), "r"(a.z), "r"(a.w), "r"(b.x), "r"(b.y));
}

static __device__ __forceinline__ u32 pack_h2(float a, float b) {
    __half2 h = __halves2half2(__float2half_rn(a), __float2half_rn(b));
    return *reinterpret_cast<u32*>(&h);
}
static __device__ __forceinline__ float fast_sigmoid(float x) {
    x = fminf(fmaxf(x, -30.f), 30.f);
    float e = __expf(-x);
    return __fdividef(1.f, 1.f + e);
}
static __device__ __forceinline__ float fast_tanh(float x) {
    x = fminf(fmaxf(x, -15.f), 15.f);
    float e = __expf(2.f * x);
    return __fdividef(e - 1.f, e + 1.f);
}

__global__ void __launch_bounds__(THREADS, 1)
lstm_mma_kernel(const float* __restrict__ x,  const float* __restrict__ Wi,
                const float* __restrict__ Wh, const float* __restrict__ b,
                const float* __restrict__ Wd, const float* __restrict__ bd,
                float* __restrict__ out)
{
    extern __shared__ char smem[];
    const int tid  = threadIdx.x;
    const int w    = tid >> 5;            // warp 0..15; owns gate rows [32w, 32w+32)
    const int lane = tid & 31;
    const int g    = lane >> 2;           // fragment group id
    const int q    = lane & 3;            // thread-in-group
    const int r0   = blockIdx.x * RPB;

    // ================= prologue: pack A fragments =================
    // A = Wh^T : A[j][k] = Wh[k*GATES + j]
    // fp16 hi frags: frag f = mt*8+kt (mt m16-tile 0..31, kt k16-tile 0..7)
    for (int ss = tid; ss < 256 * 32; ss += THREADS) {
        int f = ss >> 5, l = ss & 31;
        int kt = f & 7;
        int gg = l >> 2, qq = l & 3;
        int jb = (f >> 3) * 16, kb = kt * 16;
        int j0 = jb + gg, j1 = j0 + 8;
        int c0 = kb + 2 * qq, c2 = c0 + 8;
        uint4 v;
        v.x = pack_h2(Wh[c0 * GATES + j0], Wh[(c0 + 1) * GATES + j0]);
        v.y = pack_h2(Wh[c0 * GATES + j1], Wh[(c0 + 1) * GATES + j1]);
        v.z = pack_h2(Wh[c2 * GATES + j0], Wh[(c2 + 1) * GATES + j0]);
        v.w = pack_h2(Wh[c2 * GATES + j1], Wh[(c2 + 1) * GATES + j1]);
        *reinterpret_cast<uint4*>(smem + AH_OFF + f * 512 + l * 16) = v;
    }
    // e4m3 lo frags (scaled 2^12): frag f = mt*4+k8 (k8 k32-tile 0..3)
    for (int ss = tid; ss < 128 * 32; ss += THREADS) {
        int f = ss >> 5, l = ss & 31;
        int k8 = f & 3;
        int gg = l >> 2, qq = l & 3;
        int jb = (f >> 2) * 16, kb = k8 * 32;
        int j0 = jb + gg, j1 = j0 + 8;
        u32 regs[4];
#pragma unroll
        for (int rr = 0; rr < 4; rr++) {
            int row = (rr & 1) ? j1 : j0;
            int cb  = kb + 4 * qq + ((rr >> 1) ? 16 : 0);
            u32 v = 0;
#pragma unroll
            for (int t = 0; t < 4; t++) {
                float wv = Wh[(cb + t) * GATES + row];
                float hi = __half2float(__float2half_rn(wv));
                float lo = (wv - hi) * SCALE_LO;
                u32 byte = (u32)__nv_cvt_float_to_fp8(lo, __NV_SATFINITE, __NV_E4M3);
                v |= byte << (8 * t);
            }
            regs[rr] = v;
        }
        *reinterpret_cast<uint4*>(smem + ALO_OFF + f * 512 + l * 16) =
            make_uint4(regs[0], regs[1], regs[2], regs[3]);
    }
    // zero B tiles (h0 = 0)
    for (int i = tid; i < (2048 + 2048 + 1024) / 4; i += THREADS)
        *reinterpret_cast<u32*>(smem + BH_OFF + i * 4) = 0;
    // x for step 0
    if (tid < RPB)
        *reinterpret_cast<float*>(smem + XBUF_OFF + tid * 4) = x[(r0 + tid) * SEQ];

    // per-thread Wi/b constants for epilogue rows
    const int jr0 = 32 * w + g;            // mt0 row a
    float wi00 = Wi[jr0],      b00 = b[jr0];
    float wi01 = Wi[jr0 + 8],  b01 = b[jr0 + 8];
    float wi10 = Wi[jr0 + 16], b10 = b[jr0 + 16];
    float wi11 = Wi[jr0 + 24], b11 = b[jr0 + 24];
    const bool is_tanh = (w >> 2) == 2;    // warps 8-11 hold the g gate

    // update-role constants (tid < 128): B-fragment write offsets for hid p
    const int p = tid;
    int off_h = 0, off_8 = 0;
    if (p < HID) {
        int pi = p & 15, pj = pi & 7;
        off_h = (p >> 4) * 256 + (pj >> 1) * 8 + (pi >> 3) * 4 + (pj & 1) * 2;
        int p8 = p & 31, pj8 = p8 & 15;
        off_8 = (p >> 5) * 256 + (pj8 >> 2) * 8 + (p8 >> 4) * 4 + (pj8 & 3);
    }
    float c_st[RPB], h_st[RPB];
#pragma unroll
    for (int r = 0; r < RPB; r++) { c_st[r] = 0.f; h_st[r] = 0.f; }

    __syncthreads();

    const char* AH  = smem + AH_OFF  + (w * 2) * 8 * 512;  // my 2 m-tiles, hi
    const char* ALO = smem + ALO_OFF + (w * 2) * 4 * 512;  // my 2 m-tiles, lo

    // ================= sequential loop =================
    for (int s = 0; s < SEQ; s++) {
        // prefetch next x (consumed after sync2, next iter)
        float xn = 0.f;
        if (tid < RPB && s + 1 < SEQ) xn = x[(r0 + tid) * SEQ + s + 1];

        // ---- load B fragments (built by update role last iter) ----
        uint2 bh[8], bl[8], b8[4];
#pragma unroll
        for (int kt = 0; kt < 8; kt++) {
            bh[kt] = *reinterpret_cast<const uint2*>(smem + BH_OFF + kt * 256 + lane * 8);
            bl[kt] = *reinterpret_cast<const uint2*>(smem + BL_OFF + kt * 256 + lane * 8);
        }
#pragma unroll
        for (int k8 = 0; k8 < 4; k8++)
            b8[k8] = *reinterpret_cast<const uint2*>(smem + B8_OFF + k8 * 256 + lane * 8);

        // ---- 3-pass MMA: D = Ah*Bh ; Dc = Ah*Bl + Alo*B8 ----
        float d[2][4], dc[2][4];
#pragma unroll
        for (int mt = 0; mt < 2; mt++) {
#pragma unroll
            for (int i = 0; i < 4; i++) { d[mt][i] = 0.f; dc[mt][i] = 0.f; }
#pragma unroll
            for (int kt = 0; kt < 8; kt++) {
                uint4 a = *reinterpret_cast<const uint4*>(AH + (mt * 8 + kt) * 512 + lane * 16);
                mma_f16(d[mt],  a, bh[kt]);
                mma_f16(dc[mt], a, bl[kt]);
            }
#pragma unroll
            for (int k8 = 0; k8 < 4; k8++) {
                uint4 a = *reinterpret_cast<const uint4*>(ALO + (mt * 4 + k8) * 512 + lane * 16);
                mma_e4m3(dc[mt], a, b8[k8]);
            }
        }

        // ---- epilogue: + x*Wi + b, activation, store to gs[col][row] ----
        const float* xs = reinterpret_cast<const float*>(smem + XBUF_OFF + (s & 1) * 32);
        float x0 = xs[2 * q], x1 = xs[2 * q + 1];
        float* gs = reinterpret_cast<float*>(smem + GS_OFF);
#pragma unroll
        for (int mt = 0; mt < 2; mt++) {
            int ja = 32 * w + 16 * mt + g;           // rows ja, ja+8
            float wia = mt ? wi10 : wi00, ba = mt ? b10 : b00;
            float wib = mt ? wi11 : wi01, bb = mt ? b11 : b01;
            float e0 = d[mt][0] + dc[mt][0] * INV_SCALE_LO + x0 * wia + ba;
            float e1 = d[mt][1] + dc[mt][1] * INV_SCALE_LO + x1 * wia + ba;
            float e2 = d[mt][2] + dc[mt][2] * INV_SCALE_LO + x0 * wib + bb;
            float e3 = d[mt][3] + dc[mt][3] * INV_SCALE_LO + x1 * wib + bb;
            if (is_tanh) {
                e0 = fast_tanh(e0); e1 = fast_tanh(e1);
                e2 = fast_tanh(e2); e3 = fast_tanh(e3);
            } else {
                e0 = fast_sigmoid(e0); e1 = fast_sigmoid(e1);
                e2 = fast_sigmoid(e2); e3 = fast_sigmoid(e3);
            }
            gs[(2 * q) * GATES + ja]         = e0;
            gs[(2 * q + 1) * GATES + ja]     = e1;
            gs[(2 * q) * GATES + ja + 8]     = e2;
            gs[(2 * q + 1) * GATES + ja + 8] = e3;
        }

        __syncthreads();   // gates visible; all B-fragment reads complete

        // ---- update role (tid < 128): c,h update + write new B frags ----
        if (p < HID) {
            const float* gsr = reinterpret_cast<const float*>(smem + GS_OFF);
#pragma unroll
            for (int r = 0; r < RPB; r++) {
                float iv = gsr[r * GATES + p];
                float fv = gsr[r * GATES + p + 128];
                float gg = gsr[r * GATES + p + 256];
                float ov = gsr[r * GATES + p + 384];
                float c  = fv * c_st[r] + iv * gg;
                c_st[r]  = c;
                float h  = ov * fast_tanh(c);
                h_st[r]  = h;
                __half hh = __float2half_rn(h);
                float  hf = __half2float(hh);
                __half hl = __float2half_rn((h - hf) * SCALE_LO);
                *reinterpret_cast<unsigned short*>(smem + BH_OFF + off_h + r * 32) =
                    *reinterpret_cast<unsigned short*>(&hh);
                *reinterpret_cast<unsigned short*>(smem + BL_OFF + off_h + r * 32) =
                    *reinterpret_cast<unsigned short*>(&hl);
                smem[B8_OFF + off_8 + r * 32] =
                    (char)__nv_cvt_float_to_fp8(h, __NV_SATFINITE, __NV_E4M3);
            }
            if (p < RPB && s + 1 < SEQ)
                *reinterpret_cast<float*>(smem + XBUF_OFF + ((s + 1) & 1) * 32 + p * 4) = xn;
        }

        __syncthreads();   // new B tiles + x published
    }

    // ================= output: out[r] = h . Wd + bd =================
    if (p < HID) {
        float wd = Wd[p];
        float* red = reinterpret_cast<float*>(smem + RED_OFF);
#pragma unroll
        for (int r = 0; r < RPB; r++) red[p * 8 + r] = h_st[r] * wd;
    }
    __syncthreads();
    if (tid < RPB) {
        const float* red = reinterpret_cast<const float*>(smem + RED_OFF);
        float sum = 0.f;
        for (int pp = 0; pp < HID; pp++) sum += red[pp * 8 + tid];
        out[r0 + tid] = sum + bd[0];
    }
}

extern "C" void kernel_launch(void* const* d_in, const int* in_sizes, int n_in,
                              void* d_out, int out_size)
{
    (void)in_sizes; (void)n_in; (void)out_size;
    const float* x  = (const float*)d_in[0];
    const float* Wi = (const float*)d_in[1];
    const float* Wh = (const float*)d_in[2];
    const float* b  = (const float*)d_in[3];
    const float* Wd = (const float*)d_in[4];
    const float* bd = (const float*)d_in[5];
    float* out = (float*)d_out;

    cudaFuncSetAttribute(lstm_mma_kernel,
                         cudaFuncAttributeMaxDynamicSharedMemorySize, SMEM_TOTAL);
    lstm_mma_kernel<<<NCTA, THREADS, SMEM_TOTAL>>>(x, Wi, Wh, b, Wd, bd, out);
}

// round 4
// speedup vs baseline: 3.0198x; 1.4065x over previous
#include <cuda_runtime.h>
#include <cuda_fp16.h>

#define THREADS 1024
#define RPB     8
#define NCTA    128
#define SEQ     1024
#define GATES   512
#define HID     128

// ---- smem byte offsets ----
#define AH_OFF    0         // A fp16 fragments: 256 frags * 512B = 131072
#define BH_OFF    131072    // B_hi fp16 frags: 8 * 256B = 2048
#define BL_OFF    133120    // B_lo fp16 frags: 2048
#define GS_OFF    135168    // activated gates [8 cols][512 rows] f32 = 16384
#define XBUF_OFF  151552    // x double buffer 2*8 f32 = 64
#define RED_OFF   151616    // output reduction 128*8 f32 = 4096
#define SMEM_TOTAL 155712

#define SCALE_LO     4096.0f
#define INV_SCALE_LO 0.000244140625f
#define LOG2E        1.4426950408889634f

typedef unsigned int u32;

static __device__ __forceinline__ void mma_f16(float* d, const uint4& a, const uint2& b) {
    asm volatile("mma.sync.aligned.m16n8k16.row.col.f32.f16.f16.f32 "
        "{%0,%1,%2,%3}, {%4,%5,%6,%7}, {%8,%9}, {%0,%1,%2,%3};"
        : "+f"(d[0]), "+f"(d[1]), "+f"(d[2]), "+f"(d[3])
        : "r"(a.x), "r"(a.y), "r"(a.z), "r"(a.w), "r"(b.x), "r"(b.y));
}
static __device__ __forceinline__ float ex2f(float x) {
    float r; asm("ex2.approx.f32 %0, %1;" : "=f"(r) : "f"(x)); return r;
}
static __device__ __forceinline__ float rcpf(float x) {
    float r; asm("rcp.approx.f32 %0, %1;" : "=f"(r) : "f"(x)); return r;
}
static __device__ __forceinline__ u32 pack_h2(float a, float b) {
    __half2 h = __halves2half2(__float2half_rn(a), __float2half_rn(b));
    return *reinterpret_cast<u32*>(&h);
}
static __device__ __forceinline__ float fast_tanh1(float x) {   // single value (update)
    x = fminf(fmaxf(x, -15.f), 15.f);
    float e = ex2f(x * (2.f * LOG2E));
    return (e - 1.f) * rcpf(e + 1.f);
}

__global__ void __launch_bounds__(THREADS, 1)
lstm_mma32_kernel(const float* __restrict__ x,  const float* __restrict__ Wi,
                  const float* __restrict__ Wh, const float* __restrict__ b,
                  const float* __restrict__ Wd, const float* __restrict__ bd,
                  float* __restrict__ out)
{
    extern __shared__ char smem[];
    const int tid  = threadIdx.x;
    const int w    = tid >> 5;           // warp = m-tile 0..31 (gate rows [16w,16w+16))
    const int lane = tid & 31;
    const int g    = lane >> 2;
    const int q    = lane & 3;
    const int r0   = blockIdx.x * RPB;

    // ============ prologue: pack A = Wh^T fp16 fragments ============
    // frag f = mt*8 + kt; element layout matches mma m16n8k16 A operand.
    for (int ss = tid; ss < 256 * 32; ss += THREADS) {
        int f = ss >> 5, l = ss & 31;
        int kt = f & 7;
        int gg = l >> 2, qq = l & 3;
        int jb = (f >> 3) * 16, kb = kt * 16;
        int j0 = jb + gg, j1 = j0 + 8;
        int c0 = kb + 2 * qq, c2 = c0 + 8;
        uint4 v;
        v.x = pack_h2(Wh[c0 * GATES + j0], Wh[(c0 + 1) * GATES + j0]);
        v.y = pack_h2(Wh[c0 * GATES + j1], Wh[(c0 + 1) * GATES + j1]);
        v.z = pack_h2(Wh[c2 * GATES + j0], Wh[(c2 + 1) * GATES + j0]);
        v.w = pack_h2(Wh[c2 * GATES + j1], Wh[(c2 + 1) * GATES + j1]);
        *reinterpret_cast<uint4*>(smem + AH_OFF + f * 512 + l * 16) = v;
    }
    // zero B tiles (h0 = 0)
    for (int i = tid; i < 4096 / 4; i += THREADS)
        *reinterpret_cast<u32*>(smem + BH_OFF + i * 4) = 0;
    if (tid < RPB)
        *reinterpret_cast<float*>(smem + XBUF_OFF + tid * 4) = x[(r0 + tid) * SEQ];

    // epilogue constants: my two gate rows ja, ja+8
    const int ja = 16 * w + g;
    const float wi0 = Wi[ja],     b0 = b[ja];
    const float wi1 = Wi[ja + 8], b1 = b[ja + 8];
    const bool is_tanh = ((w >> 3) == 2);    // warps 16..23 hold the g gate

    // update role: one (r_u, p_u) item per thread
    const int r_u = tid >> 7;            // 0..7 batch col
    const int p_u = tid & 127;           // hid
    const int pi = p_u & 15, pj = pi & 7;
    const int off_h = (p_u >> 4) * 256 + (pj >> 1) * 8 + (pi >> 3) * 4 + (pj & 1) * 2
                    + r_u * 32;
    float c_st = 0.f, h_st = 0.f;

    __syncthreads();

    const char* AHw = smem + AH_OFF + w * 8 * 512;

    // ============ sequential loop ============
    for (int s = 0; s < SEQ; s++) {
        float xn = 0.f;
        if (tid < RPB && s + 1 < SEQ) xn = x[(r0 + tid) * SEQ + s + 1];

        // ---- 2-pass MMA over 8 k-tiles: D = A*Bh ; Dc = A*Bl ----
        float d[4] = {0.f, 0.f, 0.f, 0.f};
        float dc[4] = {0.f, 0.f, 0.f, 0.f};
#pragma unroll
        for (int kt = 0; kt < 8; kt++) {
            uint4 a  = *reinterpret_cast<const uint4*>(AHw + kt * 512 + lane * 16);
            uint2 bh = *reinterpret_cast<const uint2*>(smem + BH_OFF + kt * 256 + lane * 8);
            uint2 bl = *reinterpret_cast<const uint2*>(smem + BL_OFF + kt * 256 + lane * 8);
            mma_f16(d,  a, bh);
            mma_f16(dc, a, bl);
        }

        // ---- epilogue: + x*Wi + b, activation (shared-rcp), store gates ----
        const float* xs = reinterpret_cast<const float*>(smem + XBUF_OFF + (s & 1) * 32);
        float x0 = xs[2 * q], x1 = xs[2 * q + 1];
        float pre0 = d[0] + dc[0] * INV_SCALE_LO + x0 * wi0 + b0;
        float pre1 = d[1] + dc[1] * INV_SCALE_LO + x1 * wi0 + b0;
        float pre2 = d[2] + dc[2] * INV_SCALE_LO + x0 * wi1 + b1;
        float pre3 = d[3] + dc[3] * INV_SCALE_LO + x1 * wi1 + b1;

        float o0, o1, o2, o3;
        if (is_tanh) {
            // tanh_i = (E_i - 1)/(E_i + 1), E = exp(2x); one rcp for 4 divisions
            float e0 = ex2f(fminf(fmaxf(pre0, -8.f), 8.f) * (2.f * LOG2E));
            float e1 = ex2f(fminf(fmaxf(pre1, -8.f), 8.f) * (2.f * LOG2E));
            float e2 = ex2f(fminf(fmaxf(pre2, -8.f), 8.f) * (2.f * LOG2E));
            float e3 = ex2f(fminf(fmaxf(pre3, -8.f), 8.f) * (2.f * LOG2E));
            float d0 = e0 + 1.f, d1 = e1 + 1.f, d2 = e2 + 1.f, d3 = e3 + 1.f;
            float p01 = d0 * d1, p23 = d2 * d3;
            float r = rcpf(p01 * p23);
            o0 = (e0 - 1.f) * (r * d1 * p23);
            o1 = (e1 - 1.f) * (r * d0 * p23);
            o2 = (e2 - 1.f) * (r * p01 * d3);
            o3 = (e3 - 1.f) * (r * p01 * d2);
        } else {
            // sigmoid_i = 1/(1 + exp(-x)); one rcp for 4 divisions
            float e0 = ex2f(fminf(fmaxf(pre0, -14.f), 14.f) * (-LOG2E));
            float e1 = ex2f(fminf(fmaxf(pre1, -14.f), 14.f) * (-LOG2E));
            float e2 = ex2f(fminf(fmaxf(pre2, -14.f), 14.f) * (-LOG2E));
            float e3 = ex2f(fminf(fmaxf(pre3, -14.f), 14.f) * (-LOG2E));
            float d0 = e0 + 1.f, d1 = e1 + 1.f, d2 = e2 + 1.f, d3 = e3 + 1.f;
            float p01 = d0 * d1, p23 = d2 * d3;
            float r = rcpf(p01 * p23);
            o0 = r * d1 * p23;
            o1 = r * d0 * p23;
            o2 = r * p01 * d3;
            o3 = r * p01 * d2;
        }
        float* gs = reinterpret_cast<float*>(smem + GS_OFF);
        gs[(2 * q)     * GATES + ja]     = o0;
        gs[(2 * q + 1) * GATES + ja]     = o1;
        gs[(2 * q)     * GATES + ja + 8] = o2;
        gs[(2 * q + 1) * GATES + ja + 8] = o3;

        __syncthreads();   // gates visible; B-frag reads complete

        // ---- update: 1 item per thread; write new B frags (fp16 hi/lo) ----
        {
            const float* gsr = reinterpret_cast<const float*>(smem + GS_OFF);
            float iv = gsr[r_u * GATES + p_u];
            float fv = gsr[r_u * GATES + p_u + 128];
            float gg = gsr[r_u * GATES + p_u + 256];
            float ov = gsr[r_u * GATES + p_u + 384];
            c_st = fv * c_st + iv * gg;
            float h = ov * fast_tanh1(c_st);
            h_st = h;
            __half hh = __float2half_rn(h);
            float  hf = __half2float(hh);
            __half hl = __float2half_rn((h - hf) * SCALE_LO);
            *reinterpret_cast<unsigned short*>(smem + BH_OFF + off_h) =
                *reinterpret_cast<unsigned short*>(&hh);
            *reinterpret_cast<unsigned short*>(smem + BL_OFF + off_h) =
                *reinterpret_cast<unsigned short*>(&hl);
            if (tid < RPB && s + 1 < SEQ)
                *reinterpret_cast<float*>(smem + XBUF_OFF + ((s + 1) & 1) * 32 + tid * 4) = xn;
        }

        __syncthreads();   // new B tiles + x published
    }

    // ============ output: out[r] = h . Wd + bd ============
    {
        float* red = reinterpret_cast<float*>(smem + RED_OFF);
        red[p_u * 8 + r_u] = h_st * Wd[p_u];
    }
    __syncthreads();
    if (tid < RPB) {
        const float* red = reinterpret_cast<const float*>(smem + RED_OFF);
        float sum = 0.f;
        for (int pp = 0; pp < HID; pp++) sum += red[pp * 8 + tid];
        out[r0 + tid] = sum + bd[0];
    }
}

extern "C" void kernel_launch(void* const* d_in, const int* in_sizes, int n_in,
                              void* d_out, int out_size)
{
    (void)in_sizes; (void)n_in; (void)out_size;
    const float* x  = (const float*)d_in[0];
    const float* Wi = (const float*)d_in[1];
    const float* Wh = (const float*)d_in[2];
    const float* b  = (const float*)d_in[3];
    const float* Wd = (const float*)d_in[4];
    const float* bd = (const float*)d_in[5];
    float* out = (float*)d_out;

    cudaFuncSetAttribute(lstm_mma32_kernel,
                         cudaFuncAttributeMaxDynamicSharedMemorySize, SMEM_TOTAL);
    lstm_mma32_kernel<<<NCTA, THREADS, SMEM_TOTAL>>>(x, Wi, Wh, b, Wd, bd, out);
}

// round 5
// speedup vs baseline: 4.5526x; 1.5076x over previous
#include <cuda_runtime.h>
#include <cuda_fp16.h>

#define THREADS 512
#define RPB     8
#define NCTA    128
#define SEQ     1024
#define GATES   512
#define HID     128

// ---- smem byte offsets (tiny now: A lives in registers) ----
#define B_OFF     0         // fused B frags: 8 kt * 512B (per lane 16B = bh|bl)
#define GS_OFF    4096      // gates [8 rows][516 words f32] = 16512
#define XBUF_OFF  20608     // x double buffer 2*8 f32
#define RED_OFF   20672     // output reduction 128*8 f32
#define SMEM_TOTAL 24768

#define GS_STRIDE 516       // words; conflict-free for both access patterns

#define SCALE_LO     4096.0f
#define INV_SCALE_LO 0.000244140625f
#define LOG2E        1.4426950408889634f

typedef unsigned int u32;

static __device__ __forceinline__ void mma_f16(float* d, const uint4& a, u32 b0, u32 b1) {
    asm volatile("mma.sync.aligned.m16n8k16.row.col.f32.f16.f16.f32 "
        "{%0,%1,%2,%3}, {%4,%5,%6,%7}, {%8,%9}, {%0,%1,%2,%3};"
        : "+f"(d[0]), "+f"(d[1]), "+f"(d[2]), "+f"(d[3])
        : "r"(a.x), "r"(a.y), "r"(a.z), "r"(a.w), "r"(b0), "r"(b1));
}
static __device__ __forceinline__ float ex2f(float x) {
    float r; asm("ex2.approx.f32 %0, %1;" : "=f"(r) : "f"(x)); return r;
}
static __device__ __forceinline__ float rcpf(float x) {
    float r; asm("rcp.approx.f32 %0, %1;" : "=f"(r) : "f"(x)); return r;
}
static __device__ __forceinline__ u32 pack_h2(float a, float b) {
    __half2 h = __halves2half2(__float2half_rn(a), __float2half_rn(b));
    return *reinterpret_cast<u32*>(&h);
}
static __device__ __forceinline__ float fast_tanh1(float x) {
    x = fminf(fmaxf(x, -15.f), 15.f);
    float e = ex2f(x * (2.f * LOG2E));
    return (e - 1.f) * rcpf(e + 1.f);
}

// activation for 4 values with ONE rcp (shared-reciprocal)
static __device__ __forceinline__ void act4(float* v, bool is_tanh) {
    if (is_tanh) {
        float e0 = ex2f(fminf(fmaxf(v[0], -8.f), 8.f) * (2.f * LOG2E));
        float e1 = ex2f(fminf(fmaxf(v[1], -8.f), 8.f) * (2.f * LOG2E));
        float e2 = ex2f(fminf(fmaxf(v[2], -8.f), 8.f) * (2.f * LOG2E));
        float e3 = ex2f(fminf(fmaxf(v[3], -8.f), 8.f) * (2.f * LOG2E));
        float d0 = e0 + 1.f, d1 = e1 + 1.f, d2 = e2 + 1.f, d3 = e3 + 1.f;
        float p01 = d0 * d1, p23 = d2 * d3;
        float r = rcpf(p01 * p23);
        v[0] = (e0 - 1.f) * (r * d1 * p23);
        v[1] = (e1 - 1.f) * (r * d0 * p23);
        v[2] = (e2 - 1.f) * (r * p01 * d3);
        v[3] = (e3 - 1.f) * (r * p01 * d2);
    } else {
        float e0 = ex2f(fminf(fmaxf(v[0], -14.f), 14.f) * (-LOG2E));
        float e1 = ex2f(fminf(fmaxf(v[1], -14.f), 14.f) * (-LOG2E));
        float e2 = ex2f(fminf(fmaxf(v[2], -14.f), 14.f) * (-LOG2E));
        float e3 = ex2f(fminf(fmaxf(v[3], -14.f), 14.f) * (-LOG2E));
        float d0 = e0 + 1.f, d1 = e1 + 1.f, d2 = e2 + 1.f, d3 = e3 + 1.f;
        float p01 = d0 * d1, p23 = d2 * d3;
        float r = rcpf(p01 * p23);
        v[0] = r * d1 * p23;
        v[1] = r * d0 * p23;
        v[2] = r * p01 * d3;
        v[3] = r * p01 * d2;
    }
}

__global__ void __launch_bounds__(THREADS, 1)
lstm_areg_kernel(const float* __restrict__ x,  const float* __restrict__ Wi,
                 const float* __restrict__ Wh, const float* __restrict__ b,
                 const float* __restrict__ Wd, const float* __restrict__ bd,
                 float* __restrict__ out)
{
    extern __shared__ char smem[];
    const int tid  = threadIdx.x;
    const int w    = tid >> 5;           // warp 0..15, owns gate rows [32w, 32w+32)
    const int lane = tid & 31;
    const int g    = lane >> 2;
    const int q    = lane & 3;
    const int r0   = blockIdx.x * RPB;

    // ============ prologue: A = Wh^T fp16 fragments -> REGISTERS ============
    uint4 areg[2][8];                    // [m-tile][k-tile], 64 regs
#pragma unroll
    for (int mt = 0; mt < 2; mt++) {
        int jb = (2 * w + mt) * 16;
        int j0 = jb + g, j1 = j0 + 8;
#pragma unroll
        for (int kt = 0; kt < 8; kt++) {
            int c0 = kt * 16 + 2 * q, c2 = c0 + 8;
            areg[mt][kt].x = pack_h2(Wh[c0 * GATES + j0], Wh[(c0 + 1) * GATES + j0]);
            areg[mt][kt].y = pack_h2(Wh[c0 * GATES + j1], Wh[(c0 + 1) * GATES + j1]);
            areg[mt][kt].z = pack_h2(Wh[c2 * GATES + j0], Wh[(c2 + 1) * GATES + j0]);
            areg[mt][kt].w = pack_h2(Wh[c2 * GATES + j1], Wh[(c2 + 1) * GATES + j1]);
        }
    }

    // zero fused B tiles (h0 = 0)
    for (int i = tid; i < 4096 / 4; i += THREADS)
        *reinterpret_cast<u32*>(smem + B_OFF + i * 4) = 0;
    if (tid < RPB)
        *reinterpret_cast<float*>(smem + XBUF_OFF + tid * 4) = x[(r0 + tid) * SEQ];

    // epilogue constants: 4 gate rows ja(mt) = 32w + 16mt + g (+8)
    float wic[4], bc[4];
#pragma unroll
    for (int mt = 0; mt < 2; mt++) {
        int ja = 32 * w + 16 * mt + g;
        wic[2 * mt]     = Wi[ja];     bc[2 * mt]     = b[ja];
        wic[2 * mt + 1] = Wi[ja + 8]; bc[2 * mt + 1] = b[ja + 8];
    }
    const bool is_tanh = ((w >> 2) == 2);    // warps 8..11 hold the g gate

    // update role: 2 items per thread: (p_u, r_u) and (p_u, r_u+4)
    const int r_u = tid >> 7;            // 0..3
    const int p_u = tid & 127;
    const int pi = p_u & 15, pj = pi & 7;
    const int Fb = (pj >> 1) * 8 + (pi >> 3) * 4 + (pj & 1) * 2;
    const int F0 = Fb + r_u * 32;
    const int off_b0 = (p_u >> 4) * 512 + (F0 >> 3) * 16 + (F0 & 7);  // hi; lo = +8
    const int off_b1 = off_b0 + 256;     // item 2 (r_u+4): F += 128 -> lane += 16
    float c_st[2] = {0.f, 0.f}, h_st[2] = {0.f, 0.f};

    __syncthreads();

    // ============ sequential loop ============
    for (int s = 0; s < SEQ; s++) {
        float xn = 0.f;
        if (tid < RPB && s + 1 < SEQ) xn = x[(r0 + tid) * SEQ + s + 1];

        // ---- MMA: D(mt) = A*Bh ; Dc(mt) = A*Bl over 8 k-tiles ----
        float d0[4] = {0,0,0,0}, dc0[4] = {0,0,0,0};
        float d1[4] = {0,0,0,0}, dc1[4] = {0,0,0,0};
#pragma unroll
        for (int kt = 0; kt < 8; kt++) {
            uint4 bv = *reinterpret_cast<const uint4*>(smem + B_OFF + kt * 512 + lane * 16);
            mma_f16(d0,  areg[0][kt], bv.x, bv.y);
            mma_f16(dc0, areg[0][kt], bv.z, bv.w);
            mma_f16(d1,  areg[1][kt], bv.x, bv.y);
            mma_f16(dc1, areg[1][kt], bv.z, bv.w);
        }

        // ---- epilogue: + x*Wi + b, activation, store gates ----
        const float* xs = reinterpret_cast<const float*>(smem + XBUF_OFF + (s & 1) * 32);
        float x0 = xs[2 * q], x1 = xs[2 * q + 1];
        float v0[4], v1[4];
        v0[0] = d0[0] + dc0[0] * INV_SCALE_LO + x0 * wic[0] + bc[0];
        v0[1] = d0[1] + dc0[1] * INV_SCALE_LO + x1 * wic[0] + bc[0];
        v0[2] = d0[2] + dc0[2] * INV_SCALE_LO + x0 * wic[1] + bc[1];
        v0[3] = d0[3] + dc0[3] * INV_SCALE_LO + x1 * wic[1] + bc[1];
        v1[0] = d1[0] + dc1[0] * INV_SCALE_LO + x0 * wic[2] + bc[2];
        v1[1] = d1[1] + dc1[1] * INV_SCALE_LO + x1 * wic[2] + bc[2];
        v1[2] = d1[2] + dc1[2] * INV_SCALE_LO + x0 * wic[3] + bc[3];
        v1[3] = d1[3] + dc1[3] * INV_SCALE_LO + x1 * wic[3] + bc[3];
        act4(v0, is_tanh);
        act4(v1, is_tanh);

        float* gs = reinterpret_cast<float*>(smem + GS_OFF);
        {
            int ja0 = 32 * w + g, ja1 = ja0 + 16;
            int ra = 2 * q, rb = 2 * q + 1;
            gs[ra * GS_STRIDE + ja0]      = v0[0];
            gs[rb * GS_STRIDE + ja0]      = v0[1];
            gs[ra * GS_STRIDE + ja0 + 8]  = v0[2];
            gs[rb * GS_STRIDE + ja0 + 8]  = v0[3];
            gs[ra * GS_STRIDE + ja1]      = v1[0];
            gs[rb * GS_STRIDE + ja1]      = v1[1];
            gs[ra * GS_STRIDE + ja1 + 8]  = v1[2];
            gs[rb * GS_STRIDE + ja1 + 8]  = v1[3];
        }

        __syncthreads();   // gates visible; fused B reads complete

        // ---- update: 2 items/thread; write fused B frags (fp16 hi|lo) ----
        {
            const float* gsr = reinterpret_cast<const float*>(smem + GS_OFF);
#pragma unroll
            for (int it = 0; it < 2; it++) {
                int rr = r_u + 4 * it;
                float iv = gsr[rr * GS_STRIDE + p_u];
                float fv = gsr[rr * GS_STRIDE + p_u + 128];
                float gg = gsr[rr * GS_STRIDE + p_u + 256];
                float ov = gsr[rr * GS_STRIDE + p_u + 384];
                float c  = fv * c_st[it] + iv * gg;
                c_st[it] = c;
                float h  = ov * fast_tanh1(c);
                h_st[it] = h;
                __half hh = __float2half_rn(h);
                float  hf = __half2float(hh);
                __half hl = __float2half_rn((h - hf) * SCALE_LO);
                int off = it ? off_b1 : off_b0;
                *reinterpret_cast<unsigned short*>(smem + B_OFF + off) =
                    *reinterpret_cast<unsigned short*>(&hh);
                *reinterpret_cast<unsigned short*>(smem + B_OFF + off + 8) =
                    *reinterpret_cast<unsigned short*>(&hl);
            }
            if (tid < RPB && s + 1 < SEQ)
                *reinterpret_cast<float*>(smem + XBUF_OFF + ((s + 1) & 1) * 32 + tid * 4) = xn;
        }

        __syncthreads();   // new B tiles + x published
    }

    // ============ output: out[r] = h . Wd + bd ============
    {
        float* red = reinterpret_cast<float*>(smem + RED_OFF);
        float wd = Wd[p_u];
        red[p_u * 8 + r_u]     = h_st[0] * wd;
        red[p_u * 8 + r_u + 4] = h_st[1] * wd;
    }
    __syncthreads();
    if (tid < RPB) {
        const float* red = reinterpret_cast<const float*>(smem + RED_OFF);
        float sum = 0.f;
        for (int pp = 0; pp < HID; pp++) sum += red[pp * 8 + tid];
        out[r0 + tid] = sum + bd[0];
    }
}

extern "C" void kernel_launch(void* const* d_in, const int* in_sizes, int n_in,
                              void* d_out, int out_size)
{
    (void)in_sizes; (void)n_in; (void)out_size;
    const float* x  = (const float*)d_in[0];
    const float* Wi = (const float*)d_in[1];
    const float* Wh = (const float*)d_in[2];
    const float* b  = (const float*)d_in[3];
    const float* Wd = (const float*)d_in[4];
    const float* bd = (const float*)d_in[5];
    float* out = (float*)d_out;

    cudaFuncSetAttribute(lstm_areg_kernel,
                         cudaFuncAttributeMaxDynamicSharedMemorySize, SMEM_TOTAL);
    lstm_areg_kernel<<<NCTA, THREADS, SMEM_TOTAL>>>(x, Wi, Wh, b, Wd, bd, out);
}